// round 1
// baseline (speedup 1.0000x reference)
#include <cuda_runtime.h>
#include <math.h>

#define EPSV 1e-5f

constexpr int Bb  = 64;
constexpr int Vv  = 6;
constexpr int Kk  = 6;
constexpr int Dd  = 32;
constexpr int NN  = 46656;      // 6^6
constexpr int F0  = 147;        // 3*7*7
constexpr int E0  = 256;
constexpr int E1  = 1024;
constexpr int LL  = 36;         // V*K
constexpr int H1  = 1024;
constexpr int H2  = 256;
constexpr int PP  = 784;        // 16*49
constexpr int EMF = 147;        // 3*49
constexpr int TN  = 16;         // codes per block in decoder

// ---------------- scratch (static device globals; no allocation) ----------
__device__ float g_T[Vv * Kk * H1];    // folded dfc1 lookup tables (bn1-scaled)
__device__ float g_b1[H1];
__device__ float g_W2t[H1 * H2];       // dfc2^T, bn2-scaled:  [j][o]
__device__ float g_b2[H2];
__device__ float g_W1t[H2 * PP];       // dct1 (already i-major), bn3-scaled: [i][p]
__device__ float g_b3[16];
__device__ float g_e0[Bb * E0];
__device__ float g_e1[Bb * E1];
__device__ float g_s1[Bb];             // ||x_b||^2

// ---------------- prep: per-(v,k) lookup tables -------------------------
__global__ void k_prep_tables(const float* __restrict__ embeds,
                              const float* __restrict__ dfc1_w,
                              const float* __restrict__ g1,
                              const float* __restrict__ rv1) {
    int m = blockIdx.x;            // v*6 + k
    int v = m / Kk;
    const float* e = embeds + m * Dd;
    for (int j = threadIdx.x; j < H1; j += blockDim.x) {
        const float* w = dfc1_w + (size_t)j * (Vv * Dd) + v * Dd;
        float s = 0.f;
#pragma unroll
        for (int d = 0; d < Dd; d++) s += e[d] * w[d];
        float a = g1[j] * rsqrtf(rv1[j] + EPSV);
        g_T[m * H1 + j] = a * s;
    }
}

// ---------------- prep: folded biases / scaled weights / x stats --------
__global__ void k_prep_misc(
    const float* __restrict__ dfc1_b, const float* __restrict__ g1,
    const float* __restrict__ be1, const float* __restrict__ rm1, const float* __restrict__ rv1,
    const float* __restrict__ dfc2_w, const float* __restrict__ dfc2_b,
    const float* __restrict__ g2, const float* __restrict__ be2,
    const float* __restrict__ rm2, const float* __restrict__ rv2,
    const float* __restrict__ dct1_w, const float* __restrict__ dct1_b,
    const float* __restrict__ g3, const float* __restrict__ be3,
    const float* __restrict__ rm3, const float* __restrict__ rv3,
    const float* __restrict__ x) {
    int stride = gridDim.x * blockDim.x;
    int tid = blockIdx.x * blockDim.x + threadIdx.x;

    for (int j = tid; j < H1; j += stride) {
        float a = g1[j] * rsqrtf(rv1[j] + EPSV);
        g_b1[j] = a * (dfc1_b[j] - rm1[j]) + be1[j];
    }
    for (int i = tid; i < H1 * H2; i += stride) {
        int j = i >> 8, o = i & 255;
        float a = g2[o] * rsqrtf(rv2[o] + EPSV);
        g_W2t[i] = a * dfc2_w[(size_t)o * H1 + j];
    }
    for (int o = tid; o < H2; o += stride) {
        float a = g2[o] * rsqrtf(rv2[o] + EPSV);
        g_b2[o] = a * (dfc2_b[o] - rm2[o]) + be2[o];
    }
    for (int i = tid; i < H2 * PP; i += stride) {
        int o = (i % PP) / 49;
        float a = g3[o] * rsqrtf(rv3[o] + EPSV);
        g_W1t[i] = a * dct1_w[i];
    }
    for (int o = tid; o < 16; o += stride) {
        float a = g3[o] * rsqrtf(rv3[o] + EPSV);
        g_b3[o] = a * (dct1_b[o] - rm3[o]) + be3[o];
    }
    for (int b = tid; b < Bb; b += stride) {
        float s = 0.f;
        for (int r = 0; r < F0; r++) { float v = x[b * F0 + r]; s += v * v; }
        g_s1[b] = s;
    }
}

// ---------------- encoder layer 1: conv(as matmul) + BN-train + relu ----
__global__ void k_enc1(const float* __restrict__ x, const float* __restrict__ w,
                       const float* __restrict__ bias,
                       const float* __restrict__ gg, const float* __restrict__ bb) {
    int j = blockIdx.x;             // 0..255
    int b = threadIdx.x;            // 0..63
    const float* wj = w + (size_t)j * F0;
    const float* xb = x + (size_t)b * F0;
    float s = bias[j];
    for (int r = 0; r < F0; r++) s += xb[r] * wj[r];

    __shared__ float red[2];
    float t = s;
    for (int off = 16; off; off >>= 1) t += __shfl_down_sync(0xffffffffu, t, off);
    if ((b & 31) == 0) red[b >> 5] = t;
    __syncthreads();
    float m = (red[0] + red[1]) * (1.f / 64.f);
    __syncthreads();
    float d = s - m;
    t = d * d;
    for (int off = 16; off; off >>= 1) t += __shfl_down_sync(0xffffffffu, t, off);
    if ((b & 31) == 0) red[b >> 5] = t;
    __syncthreads();
    float var = (red[0] + red[1]) * (1.f / 64.f);
    float y = gg[j] * d * rsqrtf(var + EPSV) + bb[j];
    g_e0[(size_t)b * E0 + j] = fmaxf(y, 0.f);
}

// ---------------- encoder layer 2: fc1 + BN-train + relu ----------------
__global__ void k_enc2(const float* __restrict__ w, const float* __restrict__ bias,
                       const float* __restrict__ gg, const float* __restrict__ bb) {
    int j = blockIdx.x;             // 0..1023
    int b = threadIdx.x;            // 0..63
    const float* wj = w + (size_t)j * E0;
    const float* xb = g_e0 + (size_t)b * E0;
    float s = bias[j];
    for (int r = 0; r < E0; r++) s += xb[r] * wj[r];

    __shared__ float red[2];
    float t = s;
    for (int off = 16; off; off >>= 1) t += __shfl_down_sync(0xffffffffu, t, off);
    if ((b & 31) == 0) red[b >> 5] = t;
    __syncthreads();
    float m = (red[0] + red[1]) * (1.f / 64.f);
    __syncthreads();
    float d = s - m;
    t = d * d;
    for (int off = 16; off; off >>= 1) t += __shfl_down_sync(0xffffffffu, t, off);
    if ((b & 31) == 0) red[b >> 5] = t;
    __syncthreads();
    float var = (red[0] + red[1]) * (1.f / 64.f);
    float y = gg[j] * d * rsqrtf(var + EPSV) + bb[j];
    g_e1[(size_t)b * E1 + j] = fmaxf(y, 0.f);
}

// ---------------- encoder head: fc2 + softmax + entropy loss ------------
__global__ void k_enc_head(const float* __restrict__ fc2_w, const float* __restrict__ fc2_b,
                           float* __restrict__ dist_out, float* __restrict__ loss_out) {
    int b = blockIdx.x;
    __shared__ float es[E1];
    __shared__ float lg[LL];
    for (int j = threadIdx.x; j < E1; j += blockDim.x) es[j] = g_e1[(size_t)b * E1 + j];
    __syncthreads();
    if (threadIdx.x < LL) {
        const float* w = fc2_w + (size_t)threadIdx.x * E1;
        float s = fc2_b[threadIdx.x];
        for (int j = 0; j < E1; j++) s += es[j] * w[j];
        lg[threadIdx.x] = s;
    }
    __syncthreads();
    if (threadIdx.x == 0) {
        float loss = 0.f;
        for (int v = 0; v < Vv; v++) {
            float mx = -1e30f;
            for (int k = 0; k < Kk; k++) mx = fmaxf(mx, lg[v * Kk + k]);
            float ex[Kk]; float se = 0.f;
            for (int k = 0; k < Kk; k++) { ex[k] = expf(lg[v * Kk + k] - mx); se += ex[k]; }
            float inv = 1.f / se;
            for (int k = 0; k < Kk; k++) {
                float p = ex[k] * inv;
                dist_out[b * LL + v * Kk + k] = p;
                loss += p * logf(p + 1e-10f);
            }
        }
        loss_out[b] = 0.1f * loss;
    }
}

// ---------------- fused decoder megakernel ------------------------------
// smem layout (floats):
//   xs[64*147] h1[16*1024] h2[16*256] h3[16*784] em[16*147] s2[16] s1[64]
//   w2[48] b3[16] kd[96](int)
constexpr int SM_XS = 0;
constexpr int SM_H1 = SM_XS + Bb * F0;
constexpr int SM_H2 = SM_H1 + TN * H1;
constexpr int SM_H3 = SM_H2 + TN * H2;
constexpr int SM_EM = SM_H3 + TN * PP;
constexpr int SM_S2 = SM_EM + TN * EMF;
constexpr int SM_S1 = SM_S2 + TN;
constexpr int SM_W2 = SM_S1 + Bb;
constexpr int SM_B3 = SM_W2 + 48;
constexpr int SM_KD = SM_B3 + 16;
constexpr int SM_FLOATS = SM_KD + TN * Vv;
constexpr int SMEM_BYTES = SM_FLOATS * 4;   // 180096 B

__global__ void __launch_bounds__(256, 1)
k_decoder(const float* __restrict__ x,
          const float* __restrict__ dct2_w, const float* __restrict__ dct2_b,
          float* __restrict__ obs) {
    extern __shared__ float sm[];
    float* xs  = sm + SM_XS;
    float* h1  = sm + SM_H1;
    float* h2  = sm + SM_H2;
    float* h3  = sm + SM_H3;
    float* em  = sm + SM_EM;
    float* s2s = sm + SM_S2;
    float* s1s = sm + SM_S1;
    float* w2s = sm + SM_W2;
    float* b3s = sm + SM_B3;
    int*   kd  = (int*)(sm + SM_KD);

    const int t  = threadIdx.x;
    const int n0 = blockIdx.x * TN;

    // stage 0: stage X, constants, digit decomposition
    for (int i = t; i < Bb * F0; i += 256) xs[i] = x[i];
    if (t < Bb) s1s[t] = g_s1[t];
    if (t < 48) w2s[t] = dct2_w[t];
    if (t < 16) b3s[t] = g_b3[t];
    if (t >= 64 && t < 64 + TN * Vv) {
        int q = t - 64, nl = q / Vv, v = q % Vv;
        const int pw[6] = {7776, 1296, 216, 36, 6, 1};
        kd[q] = ((n0 + nl) / pw[v]) % Kk;
    }
    __syncthreads();

    // stage 1: h1 = relu(sum_v T'[v][k_v] + b1')   (dfc1 + bn1 folded)
    for (int i = t; i < TN * H1; i += 256) {
        int nl = i >> 10, j = i & 1023;
        const int* kdn = kd + nl * Vv;
        float s = g_b1[j];
#pragma unroll
        for (int v = 0; v < Vv; v++) s += g_T[(v * Kk + kdn[v]) * H1 + j];
        h1[i] = fmaxf(s, 0.f);
    }
    __syncthreads();

    // stage 2: h2[nl][o] = relu(h1[nl] . W2t[:,o] + b2')   o = t
    {
        float acc[TN];
#pragma unroll
        for (int nl = 0; nl < TN; nl++) acc[nl] = 0.f;
        const float* Wp = g_W2t + t;
        for (int j = 0; j < H1; j += 4) {
            float w0 = Wp[(j + 0) * H2];
            float w1 = Wp[(j + 1) * H2];
            float w2 = Wp[(j + 2) * H2];
            float w3 = Wp[(j + 3) * H2];
#pragma unroll
            for (int nl = 0; nl < TN; nl++) {
                float4 h = *(const float4*)&h1[nl * H1 + j];   // broadcast LDS.128
                acc[nl] += h.x * w0;
                acc[nl] += h.y * w1;
                acc[nl] += h.z * w2;
                acc[nl] += h.w * w3;
            }
        }
        float b2v = g_b2[t];
#pragma unroll
        for (int nl = 0; nl < TN; nl++) h2[nl * H2 + t] = fmaxf(acc[nl] + b2v, 0.f);
    }
    __syncthreads();

    // stage 3: h3[nl][p] = relu(h2[nl] . W1t[:,p] + b3'[p/49])
    for (int p = t; p < PP; p += 256) {
        float acc[TN];
#pragma unroll
        for (int nl = 0; nl < TN; nl++) acc[nl] = 0.f;
        const float* Wp = g_W1t + p;
        for (int j = 0; j < H2; j += 4) {
            float w0 = Wp[(j + 0) * PP];
            float w1 = Wp[(j + 1) * PP];
            float w2 = Wp[(j + 2) * PP];
            float w3 = Wp[(j + 3) * PP];
#pragma unroll
            for (int nl = 0; nl < TN; nl++) {
                float4 h = *(const float4*)&h2[nl * H2 + j];
                acc[nl] += h.x * w0;
                acc[nl] += h.y * w1;
                acc[nl] += h.z * w2;
                acc[nl] += h.w * w3;
            }
        }
        float b3v = b3s[p / 49];
#pragma unroll
        for (int nl = 0; nl < TN; nl++) h3[nl * PP + p] = fmaxf(acc[nl] + b3v, 0.f);
    }
    __syncthreads();

    // stage 4: em[nl][o*49+hw] = sum_i h3[nl][i*49+hw] * w2[i][o] + dct2_b[o]
    for (int i = t; i < TN * EMF; i += 256) {
        int nl = i / EMF, r = i % EMF;
        int o = r / 49, hw = r % 49;
        float s = dct2_b[o];
        const float* h3p = h3 + nl * PP + hw;
#pragma unroll
        for (int ii = 0; ii < 16; ii++) s += h3p[ii * 49] * w2s[ii * 3 + o];
        em[i] = s;
    }
    __syncthreads();

    // stage 5a: s2[nl] = ||em[nl]||^2
    if (t < TN) {
        float s = 0.f;
        const float* e = em + t * EMF;
        for (int r = 0; r < EMF; r++) s += e[r] * e[r];
        s2s[t] = s;
    }
    __syncthreads();

    // stage 5b: obs[b][n0+nl] = -0.5*(s2 - 2 x_b.em + s1)
    for (int i = t; i < TN * Bb; i += 256) {
        int b = i / TN, nl = i % TN;        // nl fastest -> coalesced stores
        const float* xb = xs + b * F0;
        const float* e  = em + nl * EMF;
        float dot = 0.f;
        for (int r = 0; r < EMF; r++) dot += xb[r] * e[r];
        obs[(size_t)b * NN + n0 + nl] = -0.5f * (s2s[nl] - 2.f * dot + s1s[b]);
    }
}

// ---------------- launch --------------------------------------------------
extern "C" void kernel_launch(void* const* d_in, const int* in_sizes, int n_in,
                              void* d_out, int out_size) {
    const float* x      = (const float*)d_in[0];
    const float* conv_w = (const float*)d_in[1];
    const float* conv_b = (const float*)d_in[2];
    const float* ebn2_g = (const float*)d_in[3];
    const float* ebn2_b = (const float*)d_in[4];
    const float* fc1_w  = (const float*)d_in[5];
    const float* fc1_b  = (const float*)d_in[6];
    const float* ebn1_g = (const float*)d_in[7];
    const float* ebn1_b = (const float*)d_in[8];
    const float* fc2_w  = (const float*)d_in[9];
    const float* fc2_b  = (const float*)d_in[10];
    const float* embeds = (const float*)d_in[11];
    const float* dfc1_w = (const float*)d_in[12];
    const float* dfc1_b = (const float*)d_in[13];
    const float* dbn1_g = (const float*)d_in[14];
    const float* dbn1_b = (const float*)d_in[15];
    const float* dbn1_rm= (const float*)d_in[16];
    const float* dbn1_rv= (const float*)d_in[17];
    const float* dfc2_w = (const float*)d_in[18];
    const float* dfc2_b = (const float*)d_in[19];
    const float* dbn2_g = (const float*)d_in[20];
    const float* dbn2_b = (const float*)d_in[21];
    const float* dbn2_rm= (const float*)d_in[22];
    const float* dbn2_rv= (const float*)d_in[23];
    const float* dct1_w = (const float*)d_in[24];
    const float* dct1_b = (const float*)d_in[25];
    const float* dbn3_g = (const float*)d_in[26];
    const float* dbn3_b = (const float*)d_in[27];
    const float* dbn3_rm= (const float*)d_in[28];
    const float* dbn3_rv= (const float*)d_in[29];
    const float* dct2_w = (const float*)d_in[30];
    const float* dct2_b = (const float*)d_in[31];

    float* out  = (float*)d_out;
    float* obs  = out;                                  // B*N
    float* dist = out + (size_t)Bb * NN;                // B*36
    float* loss = dist + (size_t)Bb * LL;               // B

    cudaFuncSetAttribute(k_decoder, cudaFuncAttributeMaxDynamicSharedMemorySize,
                         SMEM_BYTES);

    k_prep_tables<<<Vv * Kk, 256>>>(embeds, dfc1_w, dbn1_g, dbn1_rv);
    k_prep_misc<<<256, 256>>>(dfc1_b, dbn1_g, dbn1_b, dbn1_rm, dbn1_rv,
                              dfc2_w, dfc2_b, dbn2_g, dbn2_b, dbn2_rm, dbn2_rv,
                              dct1_w, dct1_b, dbn3_g, dbn3_b, dbn3_rm, dbn3_rv,
                              x);
    k_enc1<<<E0, 64>>>(x, conv_w, conv_b, ebn2_g, ebn2_b);
    k_enc2<<<E1, 64>>>(fc1_w, fc1_b, ebn1_g, ebn1_b);
    k_enc_head<<<Bb, 128>>>(fc2_w, fc2_b, dist, loss);
    k_decoder<<<NN / TN, 256, SMEM_BYTES>>>(x, dct2_w, dct2_b, obs);
}